// round 9
// baseline (speedup 1.0000x reference)
#include <cuda_runtime.h>

// Max pool 2x2 stride 2, NCHW (32,128,224,224) fp32 -> (32,128,112,112)
// HBM-bound streaming: 822MB read + 206MB write (mandatory, zero reuse).
//
// R9: R4 optimum shape (2 float4 quads/thread, 256 threads, die-after-work,
// MLP_p1=8, .cs loads) but PLAIN write-back stores: L2 absorbs dirty output
// lines and evicts in larger bursts -> fewer DRAM read/write turnarounds
// than evict-first streaming stores.

#define IW   224
#define IH   224
#define OW   112
#define OH   112
#define OW4  28                       // float4 quads per output row
#define NC   (32 * 128)
#define TOTAL_QUADS (NC * OH * OW4)   // 12,845,056 = 512 * 25088

__device__ __forceinline__ void decode(int p, const float* __restrict__ in,
                                       const float4** r0, const float4** r1) {
    const int ow4 = p % OW4;
    const int t1  = p / OW4;
    const int oh  = t1 % OH;
    const int nc  = t1 / OH;
    const long long base = (long long)nc * (IH * IW) + (long long)(2 * oh) * IW + 8 * ow4;
    *r0 = reinterpret_cast<const float4*>(in + base);
    *r1 = reinterpret_cast<const float4*>(in + base + IW);
}

__device__ __forceinline__ float4 fmax4(float4 t0, float4 t1, float4 u0, float4 u1) {
    float4 r;
    r.x = fmaxf(fmaxf(t0.x, t0.y), fmaxf(u0.x, u0.y));
    r.y = fmaxf(fmaxf(t0.z, t0.w), fmaxf(u0.z, u0.w));
    r.z = fmaxf(fmaxf(t1.x, t1.y), fmaxf(u1.x, u1.y));
    r.w = fmaxf(fmaxf(t1.z, t1.w), fmaxf(u1.z, u1.w));
    return r;
}

__global__ __launch_bounds__(256, 8)
void pool2d_kernel(const float* __restrict__ in, float4* __restrict__ out) {
    // block covers 512 consecutive quads; thread t does quads t and t+256
    const int pA = blockIdx.x * 512 + threadIdx.x;
    const int pB = pA + 256;

    const float4 *a_r0, *a_r1, *b_r0, *b_r1;
    decode(pA, in, &a_r0, &a_r1);
    decode(pB, in, &b_r0, &b_r1);

    // 8 independent loads, front-batched, evict-first (single touch)
    const float4 a00 = __ldcs(a_r0);  const float4 a01 = __ldcs(a_r0 + 1);
    const float4 a10 = __ldcs(a_r1);  const float4 a11 = __ldcs(a_r1 + 1);
    const float4 b00 = __ldcs(b_r0);  const float4 b01 = __ldcs(b_r0 + 1);
    const float4 b10 = __ldcs(b_r1);  const float4 b11 = __ldcs(b_r1 + 1);

    // default write-back stores: L2 buffers dirty lines, lazy bulk eviction
    out[pA] = fmax4(a00, a01, a10, a11);
    out[pB] = fmax4(b00, b01, b10, b11);
}

extern "C" void kernel_launch(void* const* d_in, const int* in_sizes, int n_in,
                              void* d_out, int out_size) {
    const float* x = (const float*)d_in[0];
    float4* out = (float4*)d_out;

    const int blocks  = TOTAL_QUADS / 512;   // 25088, no tail
    const int threads = 256;

    pool2d_kernel<<<blocks, threads>>>(x, out);
}

// round 10
// speedup vs baseline: 1.0952x; 1.0952x over previous
#include <cuda_runtime.h>

// Max pool 2x2 stride 2, NCHW (32,128,224,224) fp32 -> (32,128,112,112)
// HBM-bound streaming: 822MB read + 206MB write (mandatory, zero reuse).
//
// R10: R4 optimum shape (2 float4 quads/thread, 256 threads, die-after-work,
// MLP_p1=8, .cs loads AND .cs stores — R9 proved .wb stores regress)
// + L2::256B fetch-granularity hint on loads: warps read contiguous 4KB, so
// 256B L2 fetches waste nothing but halve DRAM read-request count -> longer
// sequential read bursts at the memory controller.

#define IW   224
#define IH   224
#define OW   112
#define OH   112
#define OW4  28                       // float4 quads per output row
#define NC   (32 * 128)
#define TOTAL_QUADS (NC * OH * OW4)   // 12,845,056 = 512 * 25088

__device__ __forceinline__ float4 ldcs256(const float4* p) {
    float4 v;
    asm volatile("ld.global.cs.L2::256B.v4.f32 {%0,%1,%2,%3}, [%4];"
                 : "=f"(v.x), "=f"(v.y), "=f"(v.z), "=f"(v.w) : "l"(p));
    return v;
}

__device__ __forceinline__ void decode(int p, const float* __restrict__ in,
                                       const float4** r0, const float4** r1) {
    const int ow4 = p % OW4;
    const int t1  = p / OW4;
    const int oh  = t1 % OH;
    const int nc  = t1 / OH;
    const long long base = (long long)nc * (IH * IW) + (long long)(2 * oh) * IW + 8 * ow4;
    *r0 = reinterpret_cast<const float4*>(in + base);
    *r1 = reinterpret_cast<const float4*>(in + base + IW);
}

__device__ __forceinline__ float4 fmax4(float4 t0, float4 t1, float4 u0, float4 u1) {
    float4 r;
    r.x = fmaxf(fmaxf(t0.x, t0.y), fmaxf(u0.x, u0.y));
    r.y = fmaxf(fmaxf(t0.z, t0.w), fmaxf(u0.z, u0.w));
    r.z = fmaxf(fmaxf(t1.x, t1.y), fmaxf(u1.x, u1.y));
    r.w = fmaxf(fmaxf(t1.z, t1.w), fmaxf(u1.z, u1.w));
    return r;
}

__global__ __launch_bounds__(256, 8)
void pool2d_kernel(const float* __restrict__ in, float4* __restrict__ out) {
    // block covers 512 consecutive quads; thread t does quads t and t+256
    const int pA = blockIdx.x * 512 + threadIdx.x;
    const int pB = pA + 256;

    const float4 *a_r0, *a_r1, *b_r0, *b_r1;
    decode(pA, in, &a_r0, &a_r1);
    decode(pB, in, &b_r0, &b_r1);

    // 8 independent loads, front-batched, evict-first + 256B L2 fetch grain
    const float4 a00 = ldcs256(a_r0);  const float4 a01 = ldcs256(a_r0 + 1);
    const float4 a10 = ldcs256(a_r1);  const float4 a11 = ldcs256(a_r1 + 1);
    const float4 b00 = ldcs256(b_r0);  const float4 b01 = ldcs256(b_r0 + 1);
    const float4 b10 = ldcs256(b_r1);  const float4 b11 = ldcs256(b_r1 + 1);

    __stcs(out + pA, fmax4(a00, a01, a10, a11));
    __stcs(out + pB, fmax4(b00, b01, b10, b11));
}

extern "C" void kernel_launch(void* const* d_in, const int* in_sizes, int n_in,
                              void* d_out, int out_size) {
    const float* x = (const float*)d_in[0];
    float4* out = (float4*)d_out;

    const int blocks  = TOTAL_QUADS / 512;   // 25088, no tail
    const int threads = 256;

    pool2d_kernel<<<blocks, threads>>>(x, out);
}

// round 11
// speedup vs baseline: 1.1046x; 1.0086x over previous
#include <cuda_runtime.h>

// Max pool 2x2 stride 2, NCHW (32,128,224,224) fp32 -> (32,128,112,112)
// HBM-bound streaming: 822MB read + 206MB write — all mandatory, zero reuse.
//
// FINAL (R4 shape, verified optimum over 10 variants):
//  - die-after-work grid (25088 blocks x 256 threads): fresh blocks keep the
//    L1tex/DRAM queues full (beat persistent single-wave by 8%)
//  - 2 float4 output quads per thread, strided by blockDim within the block's
//    512-quad chunk -> warp-coalesced; 8 independent front-batched LDG.E.128.cs
//  - .cs (evict-first) on BOTH loads and stores (beat .wb and TMA bulk stores)
//  - measured: ~7.13 TB/s, 90% DRAM active = practical HBM ceiling for 4:1 R/W

#define IW   224
#define IH   224
#define OW   112
#define OH   112
#define OW4  28                       // float4 quads per output row
#define NC   (32 * 128)
#define TOTAL_QUADS (NC * OH * OW4)   // 12,845,056 = 512 * 25088

__device__ __forceinline__ void decode(int p, const float* __restrict__ in,
                                       const float4** r0, const float4** r1) {
    const int ow4 = p % OW4;
    const int t1  = p / OW4;
    const int oh  = t1 % OH;
    const int nc  = t1 / OH;
    const long long base = (long long)nc * (IH * IW) + (long long)(2 * oh) * IW + 8 * ow4;
    *r0 = reinterpret_cast<const float4*>(in + base);
    *r1 = reinterpret_cast<const float4*>(in + base + IW);
}

__device__ __forceinline__ float4 fmax4(float4 t0, float4 t1, float4 u0, float4 u1) {
    float4 r;
    r.x = fmaxf(fmaxf(t0.x, t0.y), fmaxf(u0.x, u0.y));
    r.y = fmaxf(fmaxf(t0.z, t0.w), fmaxf(u0.z, u0.w));
    r.z = fmaxf(fmaxf(t1.x, t1.y), fmaxf(u1.x, u1.y));
    r.w = fmaxf(fmaxf(t1.z, t1.w), fmaxf(u1.z, u1.w));
    return r;
}

__global__ __launch_bounds__(256, 8)
void pool2d_kernel(const float* __restrict__ in, float4* __restrict__ out) {
    // block covers 512 consecutive quads; thread t does quads t and t+256
    const int pA = blockIdx.x * 512 + threadIdx.x;
    const int pB = pA + 256;

    const float4 *a_r0, *a_r1, *b_r0, *b_r1;
    decode(pA, in, &a_r0, &a_r1);
    decode(pB, in, &b_r0, &b_r1);

    // 8 independent loads, front-batched, evict-first (single touch)
    const float4 a00 = __ldcs(a_r0);  const float4 a01 = __ldcs(a_r0 + 1);
    const float4 a10 = __ldcs(a_r1);  const float4 a11 = __ldcs(a_r1 + 1);
    const float4 b00 = __ldcs(b_r0);  const float4 b01 = __ldcs(b_r0 + 1);
    const float4 b10 = __ldcs(b_r1);  const float4 b11 = __ldcs(b_r1 + 1);

    __stcs(out + pA, fmax4(a00, a01, a10, a11));
    __stcs(out + pB, fmax4(b00, b01, b10, b11));
}

extern "C" void kernel_launch(void* const* d_in, const int* in_sizes, int n_in,
                              void* d_out, int out_size) {
    const float* x = (const float*)d_in[0];
    float4* out = (float4*)d_out;

    const int blocks  = TOTAL_QUADS / 512;   // 25088, no tail
    const int threads = 256;

    pool2d_kernel<<<blocks, threads>>>(x, out);
}

// round 12
// speedup vs baseline: 1.1088x; 1.0038x over previous
#include <cuda_runtime.h>

// Max pool 2x2 stride 2, NCHW (32,128,224,224) fp32 -> (32,128,112,112)
// HBM-bound streaming: 822MB read + 206MB write — all mandatory, zero reuse.
//
// R12: last untested shape cell — 4 quads/thread (16 front-batched LDG.128.cs,
// longest read bursts, fastest kernel time in R5) x 256-thread blocks (more
// warps/SM than R5's 128). Block covers 1024 consecutive quads, grid 12544.

#define IW   224
#define IH   224
#define OW   112
#define OH   112
#define OW4  28                       // float4 quads per output row
#define NC   (32 * 128)
#define TOTAL_QUADS (NC * OH * OW4)   // 12,845,056 = 1024 * 12544

__device__ __forceinline__ void decode(int p, const float* __restrict__ in,
                                       const float4** r0, const float4** r1) {
    const int ow4 = p % OW4;
    const int t1  = p / OW4;
    const int oh  = t1 % OH;
    const int nc  = t1 / OH;
    const long long base = (long long)nc * (IH * IW) + (long long)(2 * oh) * IW + 8 * ow4;
    *r0 = reinterpret_cast<const float4*>(in + base);
    *r1 = reinterpret_cast<const float4*>(in + base + IW);
}

__device__ __forceinline__ float4 fmax4(float4 t0, float4 t1, float4 u0, float4 u1) {
    float4 r;
    r.x = fmaxf(fmaxf(t0.x, t0.y), fmaxf(u0.x, u0.y));
    r.y = fmaxf(fmaxf(t0.z, t0.w), fmaxf(u0.z, u0.w));
    r.z = fmaxf(fmaxf(t1.x, t1.y), fmaxf(u1.x, u1.y));
    r.w = fmaxf(fmaxf(t1.z, t1.w), fmaxf(u1.z, u1.w));
    return r;
}

__global__ __launch_bounds__(256, 3)
void pool2d_kernel(const float* __restrict__ in, float4* __restrict__ out) {
    // block covers 1024 quads; thread t does quads t, t+256, t+512, t+768
    const int p0 = blockIdx.x * 1024 + threadIdx.x;
    const int p1 = p0 + 256;
    const int p2 = p0 + 512;
    const int p3 = p0 + 768;

    const float4 *a0, *a1, *b0, *b1, *c0, *c1, *d0, *d1;
    decode(p0, in, &a0, &a1);
    decode(p1, in, &b0, &b1);
    decode(p2, in, &c0, &c1);
    decode(p3, in, &d0, &d1);

    // 16 independent loads, front-batched, evict-first
    const float4 a00 = __ldcs(a0);  const float4 a01 = __ldcs(a0 + 1);
    const float4 a10 = __ldcs(a1);  const float4 a11 = __ldcs(a1 + 1);
    const float4 b00 = __ldcs(b0);  const float4 b01 = __ldcs(b0 + 1);
    const float4 b10 = __ldcs(b1);  const float4 b11 = __ldcs(b1 + 1);
    const float4 c00 = __ldcs(c0);  const float4 c01 = __ldcs(c0 + 1);
    const float4 c10 = __ldcs(c1);  const float4 c11 = __ldcs(c1 + 1);
    const float4 d00 = __ldcs(d0);  const float4 d01 = __ldcs(d0 + 1);
    const float4 d10 = __ldcs(d1);  const float4 d11 = __ldcs(d1 + 1);

    __stcs(out + p0, fmax4(a00, a01, a10, a11));
    __stcs(out + p1, fmax4(b00, b01, b10, b11));
    __stcs(out + p2, fmax4(c00, c01, c10, c11));
    __stcs(out + p3, fmax4(d00, d01, d10, d11));
}

extern "C" void kernel_launch(void* const* d_in, const int* in_sizes, int n_in,
                              void* d_out, int out_size) {
    const float* x = (const float*)d_in[0];
    float4* out = (float4*)d_out;

    const int blocks  = TOTAL_QUADS / 1024;   // 12544, no tail
    const int threads = 256;

    pool2d_kernel<<<blocks, threads>>>(x, out);
}